// round 10
// baseline (speedup 1.0000x reference)
#include <cuda_runtime.h>
#include <cuda_bf16.h>
#include <mma.h>
#include <cstdint>

using namespace nvcuda;

#define S_LEN 2048
#define D_DIM 2048
#define NH 32
#define NB 8
#define HB 256   // NH*NB

// -------- scratch (no allocations allowed) --------
__device__ float g_pq[NH * S_LEN * NB];   // [h][s][bit], pre-scaled by 2
__device__ float g_pk[NH * S_LEN * NB];
__device__ float g_pv[NH * S_LEN * NB];
__device__ float g_sumk[NH * S_LEN];
__device__ float g_op[S_LEN * HB];        // (e1-e0)*attn_out
__device__ float g_bias[D_DIM];           // e0 @ Wo

__device__ __nv_bfloat16 g_hsH[S_LEN * D_DIM];
__device__ __nv_bfloat16 g_hsL[S_LEN * D_DIM];
__device__ __nv_bfloat16 g_WgTH[D_DIM * D_DIM];  // [n][k]
__device__ __nv_bfloat16 g_WgTL[D_DIM * D_DIM];

__device__ __forceinline__ float fsigmoid(float x) {
    return 1.0f / (1.0f + __expf(-x));
}

__device__ __forceinline__ uint32_t smem_u32(const void* p) {
    uint32_t a;
    asm("{ .reg .u64 t; cvta.to.shared.u64 t, %1; cvt.u32.u64 %0, t; }" : "=r"(a) : "l"(p));
    return a;
}
__device__ __forceinline__ void cp16(uint32_t dst, const void* src) {
    asm volatile("cp.async.cg.shared.global [%0], [%1], 16;" :: "r"(dst), "l"(src));
}
__device__ __forceinline__ void cp_commit() {
    asm volatile("cp.async.commit_group;" ::: "memory");
}
template <int N> __device__ __forceinline__ void cp_wait() {
    asm volatile("cp.async.wait_group %0;" :: "n"(N) : "memory");
}

// ---------------- packing kernels ----------------
__global__ void pack_hilo(const float* __restrict__ src, __nv_bfloat16* __restrict__ h,
                          __nv_bfloat16* __restrict__ l, int n4) {
    int i = blockIdx.x * blockDim.x + threadIdx.x;
    if (i >= n4) return;
    float4 v = ((const float4*)src)[i];
    __nv_bfloat16 h0 = __float2bfloat16(v.x), h1 = __float2bfloat16(v.y);
    __nv_bfloat16 h2 = __float2bfloat16(v.z), h3 = __float2bfloat16(v.w);
    __nv_bfloat16 l0 = __float2bfloat16(v.x - __bfloat162float(h0));
    __nv_bfloat16 l1 = __float2bfloat16(v.y - __bfloat162float(h1));
    __nv_bfloat16 l2 = __float2bfloat16(v.z - __bfloat162float(h2));
    __nv_bfloat16 l3 = __float2bfloat16(v.w - __bfloat162float(h3));
    ((__nv_bfloat162*)h)[i * 2]     = __nv_bfloat162(h0, h1);
    ((__nv_bfloat162*)h)[i * 2 + 1] = __nv_bfloat162(h2, h3);
    ((__nv_bfloat162*)l)[i * 2]     = __nv_bfloat162(l0, l1);
    ((__nv_bfloat162*)l)[i * 2 + 1] = __nv_bfloat162(l2, l3);
}

// dst[n][k] = src[k][n] split hi/lo. src: [K x N] row-major.
__global__ void pack_T(const float* __restrict__ src, __nv_bfloat16* __restrict__ dh,
                       __nv_bfloat16* __restrict__ dl, int K, int N, int dstride) {
    __shared__ float t[32][33];
    int k0 = blockIdx.y * 32, n0 = blockIdx.x * 32;
    int tx = threadIdx.x, ty = threadIdx.y;
#pragma unroll
    for (int i = 0; i < 32; i += 8)
        t[ty + i][tx] = src[(size_t)(k0 + ty + i) * N + n0 + tx];
    __syncthreads();
#pragma unroll
    for (int i = 0; i < 32; i += 8) {
        float v = t[tx][ty + i];
        size_t o = (size_t)(n0 + ty + i) * dstride + k0 + tx;
        __nv_bfloat16 h = __float2bfloat16(v);
        dh[o] = h;
        dl[o] = __float2bfloat16(v - __bfloat162float(h));
    }
}

// ---------------- fp32 GEMM tile core (PROVEN in R3) ----------------
__device__ __forceinline__ void gemm_tile_128x64(
    const float* __restrict__ A, const float* __restrict__ B,
    int K, int N, int brow, int bcol, float (&acc)[8][4])
{
    __shared__ __align__(16) float As[16][132];
    __shared__ __align__(16) float Bs[16][64];
    const int tid = threadIdx.x;
    const int tx = tid & 15;
    const int ty = tid >> 4;

    const int ar = tid >> 2;
    const int ac = (tid & 3) * 4;
    const int br = tid >> 4;
    const int bc = (tid & 15) * 4;

#pragma unroll
    for (int i = 0; i < 8; ++i)
#pragma unroll
        for (int j = 0; j < 4; ++j) acc[i][j] = 0.0f;

    for (int k0 = 0; k0 < K; k0 += 16) {
        float4 a0 = *(const float4*)&A[(size_t)(brow + ar) * K + k0 + ac];
        float4 a1 = *(const float4*)&A[(size_t)(brow + ar + 64) * K + k0 + ac];
        float4 bv = *(const float4*)&B[(size_t)(k0 + br) * N + bcol + bc];
        As[ac + 0][ar] = a0.x; As[ac + 1][ar] = a0.y;
        As[ac + 2][ar] = a0.z; As[ac + 3][ar] = a0.w;
        As[ac + 0][ar + 64] = a1.x; As[ac + 1][ar + 64] = a1.y;
        As[ac + 2][ar + 64] = a1.z; As[ac + 3][ar + 64] = a1.w;
        *(float4*)&Bs[br][bc] = bv;
        __syncthreads();
#pragma unroll
        for (int k = 0; k < 16; ++k) {
            float4 x0 = *(const float4*)&As[k][ty * 8];
            float4 x1 = *(const float4*)&As[k][ty * 8 + 4];
            float4 y0 = *(const float4*)&Bs[k][tx * 4];
            float a[8] = {x0.x, x0.y, x0.z, x0.w, x1.x, x1.y, x1.z, x1.w};
            float b[4] = {y0.x, y0.y, y0.z, y0.w};
#pragma unroll
            for (int i = 0; i < 8; ++i)
#pragma unroll
                for (int j = 0; j < 4; ++j)
                    acc[i][j] = fmaf(a[i], b[j], acc[i][j]);
        }
        __syncthreads();
    }
}

// K1: QKV projections + sigmoid scatter (PROVEN in R3). grid (HB/64, S/128, 3)
__global__ void __launch_bounds__(256) qkv_kernel(
    const float* __restrict__ hs, const float* __restrict__ Wq,
    const float* __restrict__ Wk, const float* __restrict__ Wv)
{
    const float* B = (blockIdx.z == 0) ? Wq : (blockIdx.z == 1) ? Wk : Wv;
    float* O       = (blockIdx.z == 0) ? g_pq : (blockIdx.z == 1) ? g_pk : g_pv;
    const float scale = (blockIdx.z == 0) ? 2.0f : 1.0f;
    int brow = blockIdx.y * 128, bcol = blockIdx.x * 64;
    float acc[8][4];
    gemm_tile_128x64(hs, B, D_DIM, HB, brow, bcol, acc);
    int tx = threadIdx.x & 15, ty = threadIdx.x >> 4;
#pragma unroll
    for (int i = 0; i < 8; ++i) {
        int s = brow + ty * 8 + i;
#pragma unroll
        for (int j = 0; j < 4; ++j) {
            int c = bcol + tx * 4 + j;
            int h = c >> 3, d = c & 7;
            O[((size_t)h * S_LEN + s) * NB + d] = scale * fsigmoid(acc[i][j]);
        }
    }
}

// ---------------- wmma GEMM (gate only) ----------------
// C[M,N] = A x B^T. A: [M,K] bf16 row-major hi/lo, B: [N,K] bf16 row-major hi/lo.
// K extended 3x: seg0 Ah*Bh, seg1 Al*Bh, seg2 Ah*Bl.
// CTA 128x128, BK=32, 2-stage cp.async, wmma 16x16x16 (compiler-managed frags).
#define BM 128
#define BN 128
#define BK 32
#define ROWE 40                     // smem row stride in elements (32 data + 8 pad)
#define A_BYTES (128 * ROWE * 2)    // 10240
#define STAGE_BYTES (2 * A_BYTES)   // 20480
#define GEMM_SMEM (2 * STAGE_BYTES) // 40960 (< 48KB, no opt-in)

__global__ void __launch_bounds__(256) gate_wmma(
    const __nv_bfloat16* __restrict__ Ah, const __nv_bfloat16* __restrict__ Al,
    const __nv_bfloat16* __restrict__ Bh, const __nv_bfloat16* __restrict__ Bl,
    int Kreal, float* __restrict__ out)
{
    extern __shared__ __align__(128) char smem[];
    const uint32_t sbase = smem_u32(smem);
    const int tid = threadIdx.x;
    const int lane = tid & 31, wid = tid >> 5;
    const int wm = wid & 1, wn = wid >> 1;   // warp tile: 64m x 32n

    const size_t arow0 = (size_t)blockIdx.y * BM;
    const size_t brow0 = (size_t)blockIdx.x * BN;
    const int segch = Kreal / BK;
    const int nch = 3 * segch;

    const int r0 = tid >> 2, c16 = tid & 3;  // loader: rows r0, r0+64; 16B chunk c16

    auto load_chunk = [&](int c) {
        const int stage = c & 1;
        const int seg = c / segch;
        const int koff = (c - seg * segch) * BK;
        const __nv_bfloat16* As = (seg == 1) ? Al : Ah;
        const __nv_bfloat16* Bs = (seg == 2) ? Bl : Bh;
        const uint32_t sa = sbase + stage * STAGE_BYTES;
        const uint32_t sb = sa + A_BYTES;
        const __nv_bfloat16* ap = As + (arow0 + r0) * (size_t)Kreal + koff + c16 * 8;
        const __nv_bfloat16* bp = Bs + (brow0 + r0) * (size_t)Kreal + koff + c16 * 8;
        const uint32_t soff = (uint32_t)(r0 * (ROWE * 2) + c16 * 16);
        cp16(sa + soff, ap);
        cp16(sa + soff + 64 * (ROWE * 2), ap + (size_t)64 * Kreal);
        cp16(sb + soff, bp);
        cp16(sb + soff + 64 * (ROWE * 2), bp + (size_t)64 * Kreal);
    };

    wmma::fragment<wmma::accumulator, 16, 16, 16, float> acc[4][2];
#pragma unroll
    for (int mi = 0; mi < 4; ++mi)
#pragma unroll
        for (int ni = 0; ni < 2; ++ni)
            wmma::fill_fragment(acc[mi][ni], 0.0f);

    auto compute_stage = [&](int stage) {
        const __nv_bfloat16* sa = (const __nv_bfloat16*)(smem + stage * STAGE_BYTES);
        const __nv_bfloat16* sb = (const __nv_bfloat16*)(smem + stage * STAGE_BYTES + A_BYTES);
#pragma unroll
        for (int kk = 0; kk < BK; kk += 16) {
            wmma::fragment<wmma::matrix_b, 16, 16, 16, __nv_bfloat16, wmma::col_major> bf[2];
#pragma unroll
            for (int ni = 0; ni < 2; ++ni)
                wmma::load_matrix_sync(bf[ni], sb + (wn * 32 + ni * 16) * ROWE + kk, ROWE);
#pragma unroll
            for (int mi = 0; mi < 4; ++mi) {
                wmma::fragment<wmma::matrix_a, 16, 16, 16, __nv_bfloat16, wmma::row_major> af;
                wmma::load_matrix_sync(af, sa + (wm * 64 + mi * 16) * ROWE + kk, ROWE);
#pragma unroll
                for (int ni = 0; ni < 2; ++ni)
                    wmma::mma_sync(acc[mi][ni], af, bf[ni], acc[mi][ni]);
            }
        }
    };

    load_chunk(0);
    cp_commit();
    for (int c = 0; c < nch; ++c) {
        if (c + 1 < nch) load_chunk(c + 1);
        cp_commit();
        cp_wait<1>();
        __syncthreads();
        compute_stage(c & 1);
        __syncthreads();
    }

    // epilogue: stage each 16x16 acc through per-warp smem
    float* stage_c = (float*)(smem + wid * 1024);
    const int er = lane >> 1, ec0 = (lane & 1) * 8;
#pragma unroll
    for (int mi = 0; mi < 4; ++mi) {
#pragma unroll
        for (int ni = 0; ni < 2; ++ni) {
            wmma::store_matrix_sync(stage_c, acc[mi][ni], 16, wmma::mem_row_major);
            __syncwarp();
            const int r = blockIdx.y * BM + wm * 64 + mi * 16 + er;
            const int c0 = blockIdx.x * BN + wn * 32 + ni * 16 + ec0;
            float4 v0 = *(float4*)&stage_c[er * 16 + ec0];
            float4 v1 = *(float4*)&stage_c[er * 16 + ec0 + 4];
            size_t base = (size_t)r * D_DIM + c0;
            *(float4*)&out[base]     = v0;
            *(float4*)&out[base + 4] = v1;
            __syncwarp();
        }
    }
}

// ---------------- small kernels ----------------
__global__ void sumk_kernel() {
    int idx = blockIdx.x * blockDim.x + threadIdx.x;
    if (idx < NH * S_LEN) {
        const float* p = &g_pk[(size_t)idx * NB];
        float s = 0.f;
#pragma unroll
        for (int d = 0; d < NB; ++d) s += p[d];
        g_sumk[idx] = s;
    }
}

__global__ void bias_kernel(const float* __restrict__ e0, const float* __restrict__ Wo) {
    int n = blockIdx.x * blockDim.x + threadIdx.x;
    if (n < D_DIM) {
        float s = 0.f;
        for (int j = 0; j < HB; ++j) s = fmaf(e0[j], Wo[(size_t)j * D_DIM + n], s);
        g_bias[n] = s;
    }
}

// ---------------- causal attention (fp32, PROVEN in R3) ----------------
__global__ void __launch_bounds__(128) attn_kernel(
    const float* __restrict__ e0, const float* __restrict__ e1)
{
    const int h = blockIdx.y;
    const int qt = blockIdx.x;
    const int tid = threadIdx.x;
    const int q = qt * 128 + tid;

    __shared__ __align__(16) float sk[128 * 8];
    __shared__ __align__(16) float sv[128 * 8];
    __shared__ float ssum[128];

    float pq[8];
    {
        const float4* p = (const float4*)&g_pq[((size_t)h * S_LEN + q) * NB];
        float4 p0 = p[0], p1 = p[1];
        pq[0] = p0.x; pq[1] = p0.y; pq[2] = p0.z; pq[3] = p0.w;
        pq[4] = p1.x; pq[5] = p1.y; pq[6] = p1.z; pq[7] = p1.w;
    }
    float acc[8] = {0, 0, 0, 0, 0, 0, 0, 0};
    float l = 0.f;

    const float* kbase = &g_pk[(size_t)h * S_LEN * NB];
    const float* vbase = &g_pv[(size_t)h * S_LEN * NB];

    for (int kt = 0; kt <= qt; ++kt) {
        const float4* kp = (const float4*)(kbase + (size_t)kt * 128 * NB);
        const float4* vp = (const float4*)(vbase + (size_t)kt * 128 * NB);
        ((float4*)sk)[tid]       = kp[tid];
        ((float4*)sk)[tid + 128] = kp[tid + 128];
        ((float4*)sv)[tid]       = vp[tid];
        ((float4*)sv)[tid + 128] = vp[tid + 128];
        ssum[tid] = g_sumk[h * S_LEN + kt * 128 + tid];
        __syncthreads();

        const int kmax = (kt == qt) ? (tid + 1) : 128;
        const float4* sk4 = (const float4*)sk;
        const float4* sv4 = (const float4*)sv;
        for (int kk = 0; kk < kmax; ++kk) {
            float4 k0 = sk4[kk * 2];
            float4 k1 = sk4[kk * 2 + 1];
            float dot = -ssum[kk];
            dot = fmaf(pq[0], k0.x, dot); dot = fmaf(pq[1], k0.y, dot);
            dot = fmaf(pq[2], k0.z, dot); dot = fmaf(pq[3], k0.w, dot);
            dot = fmaf(pq[4], k1.x, dot); dot = fmaf(pq[5], k1.y, dot);
            dot = fmaf(pq[6], k1.z, dot); dot = fmaf(pq[7], k1.w, dot);
            float e = __expf(dot);
            l += e;
            float4 v0 = sv4[kk * 2];
            float4 v1 = sv4[kk * 2 + 1];
            acc[0] = fmaf(e, v0.x, acc[0]); acc[1] = fmaf(e, v0.y, acc[1]);
            acc[2] = fmaf(e, v0.z, acc[2]); acc[3] = fmaf(e, v0.w, acc[3]);
            acc[4] = fmaf(e, v1.x, acc[4]); acc[5] = fmaf(e, v1.y, acc[5]);
            acc[6] = fmaf(e, v1.z, acc[6]); acc[7] = fmaf(e, v1.w, acc[7]);
        }
        __syncthreads();
    }

    float inv = 1.0f / l;
    float o[8];
#pragma unroll
    for (int d = 0; d < 8; ++d) {
        int j = h * 8 + d;
        o[d] = acc[d] * inv * (e1[j] - e0[j]);
    }
    float4* outp = (float4*)&g_op[(size_t)q * HB + h * 8];
    outp[0] = make_float4(o[0], o[1], o[2], o[3]);
    outp[1] = make_float4(o[4], o[5], o[6], o[7]);
}

// K6 (PROVEN in R3): out = (g_op @ Wo + bias) * sigmoid(gate_pre)
__global__ void __launch_bounds__(256) final_kernel(
    const float* __restrict__ Wo, float* __restrict__ out)
{
    int brow = blockIdx.y * 128, bcol = blockIdx.x * 64;
    float acc[8][4];
    gemm_tile_128x64(g_op, Wo, HB, D_DIM, brow, bcol, acc);
    int tx = threadIdx.x & 15, ty = threadIdx.x >> 4;
    int c0 = bcol + tx * 4;
    float b0 = g_bias[c0], b1 = g_bias[c0 + 1], b2 = g_bias[c0 + 2], b3 = g_bias[c0 + 3];
#pragma unroll
    for (int i = 0; i < 8; ++i) {
        int r = brow + ty * 8 + i;
        size_t base = (size_t)r * D_DIM + c0;
        float4 g = *(float4*)&out[base];
        float4 v;
        v.x = (acc[i][0] + b0) * fsigmoid(g.x);
        v.y = (acc[i][1] + b1) * fsigmoid(g.y);
        v.z = (acc[i][2] + b2) * fsigmoid(g.z);
        v.w = (acc[i][3] + b3) * fsigmoid(g.w);
        *(float4*)&out[base] = v;
    }
}

// ---------------- launch ----------------
extern "C" void kernel_launch(void* const* d_in, const int* in_sizes, int n_in,
                              void* d_out, int out_size)
{
    (void)in_sizes; (void)n_in; (void)out_size;
    const float* hs = (const float*)d_in[0];
    const float* Wq = (const float*)d_in[1];
    const float* Wk = (const float*)d_in[2];
    const float* Wv = (const float*)d_in[3];
    const float* Wo = (const float*)d_in[4];
    const float* Wg = (const float*)d_in[5];
    const float* e0 = (const float*)d_in[6];
    const float* e1 = (const float*)d_in[7];
    float* out = (float*)d_out;

    dim3 tb(32, 8);
    // packs for the wmma gate path
    pack_hilo<<<(S_LEN * D_DIM / 4 + 255) / 256, 256>>>(hs, g_hsH, g_hsL, S_LEN * D_DIM / 4);
    pack_T<<<dim3(D_DIM / 32, D_DIM / 32), tb>>>(Wg, g_WgTH, g_WgTL, D_DIM, D_DIM, D_DIM);

    // qkv projections: PROVEN fp32 path
    qkv_kernel<<<dim3(HB / 64, S_LEN / 128, 3), 256>>>(hs, Wq, Wk, Wv);
    sumk_kernel<<<(NH * S_LEN + 255) / 256, 256>>>();
    bias_kernel<<<(D_DIM + 255) / 256, 256>>>(e0, Wo);

    // gate preact via wmma -> out
    gate_wmma<<<dim3(D_DIM / BN, S_LEN / BM), 256, GEMM_SMEM>>>(
        g_hsH, g_hsL, g_WgTH, g_WgTL, D_DIM, out);

    // attention -> g_op
    attn_kernel<<<dim3(S_LEN / 128, NH), 128>>>(e0, e1);

    // final: PROVEN fp32 path. out = (op @ Wo + bias) * sigmoid(out)
    final_kernel<<<dim3(D_DIM / 64, S_LEN / 128), 256>>>(Wo, out);
}